// round 2
// baseline (speedup 1.0000x reference)
#include <cuda_runtime.h>
#include <stdint.h>

// ---------------------------------------------------------------------------
// Bidirectional GRU with predictor feedback, persistent-kernel formulation.
//   B=128, T=1024, H=512.
// Grid: 128 CTAs (64 per direction), 256 threads, 120KB dyn SMEM (1 CTA/SM).
// CTA c of direction d owns hidden columns [c*8, c*8+8).
// Mask dtype is detected at runtime on-device (bool arrays may be serialized
// as int32 / float32 / uint8 by the harness).
// ---------------------------------------------------------------------------

namespace {
constexpr int kB = 128;
constexpr int kT = 1024;
constexpr int kH = 512;
constexpr int kCtaPerDir = 64;
constexpr int kNCta = 2 * kCtaPerDir;
constexpr int kThreads = 256;
constexpr int kCols = 8;              // hidden columns per CTA
constexpr int kRows = 32;             // 24 w_hh rows + 8 p_w1 rows
constexpr int kWsStride = 513;        // pad to kill SMEM bank conflicts
constexpr int kGhsStride = 132;       // 132 mod 32 == 4 -> conflict-free gate reads
constexpr int kChunk = 64;            // K-chunk staged in SMEM
constexpr int kNChunk = kH / kChunk;  // 8
constexpr int kSmemFloats = kRows * kWsStride + kChunk * kB + kRows * kGhsStride + 96 + 128;
constexpr int kSmemBytes = 120 * 1024;  // force 1 CTA/SM (2x120KB > 228KB)
static_assert(kSmemFloats * 4 <= kSmemBytes, "smem overflow");
}  // namespace

// Scratch (device globals; no allocation allowed in kernel_launch).
__device__ float g_h[2][2][kH][kB];                  // [dir][buf][k][b], 512 KB
__device__ float g_spart[2][kB][kCtaPerDir];         // predictor partial sums
__device__ unsigned int g_flags[2][kCtaPerDir * 8];  // barrier flags, 32B stride
__device__ int g_mask_mode;                          // 0=u8, 1=i32, 2=f32

// ---- packed fp32x2 helpers (sm_103a) --------------------------------------
__device__ __forceinline__ unsigned long long pk2(float v) {
  unsigned long long r;
  asm("mov.b64 %0, {%1, %1};" : "=l"(r) : "f"(v));
  return r;
}
__device__ __forceinline__ void fma2(unsigned long long& acc, unsigned long long a,
                                     unsigned long long b) {
  asm("fma.rn.f32x2 %0, %1, %2, %0;" : "+l"(acc) : "l"(a), "l"(b));
}
__device__ __forceinline__ float2 unpk(unsigned long long v) {
  float2 f;
  asm("mov.b64 {%0, %1}, %2;" : "=f"(f.x), "=f"(f.y) : "l"(v));
  return f;
}

__device__ __forceinline__ float sigmoid_fast(float v) {
  return __fdividef(1.f, 1.f + __expf(-v));
}
__device__ __forceinline__ float tanh_fast(float v) {
  // (e^{2v}-1)/(e^{2v}+1); saturates correctly for |v| large.
  return 1.f - __fdividef(2.f, 1.f + __expf(2.f * v));
}

// Per-direction grid barrier. All 64 CTAs of one direction are co-resident
// (120KB SMEM -> 1 CTA/SM, grid 128 <= 148 SMs -> single wave), so spinning
// is safe. Monotonic phase counter; flags zeroed by init kernel each launch.
__device__ __forceinline__ void group_barrier(int d, unsigned int phase, int c) {
  __syncthreads();
  if (threadIdx.x == 0) {
    asm volatile("st.release.gpu.u32 [%0], %1;" ::"l"(&g_flags[d][c * 8]), "r"(phase)
                 : "memory");
  }
  if (threadIdx.x < kCtaPerDir) {
    const unsigned int* fp = &g_flags[d][threadIdx.x * 8];
    unsigned int v;
    do {
      asm volatile("ld.acquire.gpu.u32 %0, [%1];" : "=r"(v) : "l"(fp) : "memory");
    } while (v < phase);
  }
  __syncthreads();
}

__global__ void init_kernel(const void* __restrict__ mask) {
  int idx = blockIdx.x * blockDim.x + threadIdx.x;
  if (idx < kH * kB) {
    (&g_h[0][0][0][0])[idx] = 0.f;  // forward h0 = 0
    (&g_h[1][0][0][0])[idx] = 0.f;  // backward h0 = 0
  }
  if (idx < 2 * kCtaPerDir * 8) (&g_flags[0][0])[idx] = 0u;
  if (idx == 0) {
    // Detect mask serialization. Bool arrays may arrive as int32 {0,1},
    // float32 {0.0,1.0}, or raw uint8 {0,1}. Check the first 64 elements.
    const int* i32 = (const int*)mask;
    const float* f32 = (const float*)mask;
    bool is_i32 = true, is_f32 = true;
    for (int i = 0; i < 64; ++i) {
      int v = i32[i];
      if (v != 0 && v != 1) is_i32 = false;
      float f = f32[i];
      if (!(f == 0.f || f == 1.f)) is_f32 = false;
    }
    g_mask_mode = is_i32 ? 1 : (is_f32 ? 2 : 0);
  }
}

__global__ void __launch_bounds__(kThreads, 1)
bidgru_kernel(const float* __restrict__ x, const void* __restrict__ mask,
              const float* __restrict__ wf_ih, const float* __restrict__ wf_hh,
              const float* __restrict__ bf_ih, const float* __restrict__ bf_hh,
              const float* __restrict__ wb_ih, const float* __restrict__ wb_hh,
              const float* __restrict__ bb_ih, const float* __restrict__ bb_hh,
              const float* __restrict__ p_w1, const float* __restrict__ p_b1,
              const float* __restrict__ p_w2, const float* __restrict__ p_b2,
              float* __restrict__ out) {
  extern __shared__ float smem[];
  float* ws = smem;                         // [32][513] weight slice
  float* hs = ws + kRows * kWsStride;       // [64][128] h chunk (k-major)
  float* ghs = hs + kChunk * kB;            // [32][132] gh / predictor terms
  float* sb = ghs + kRows * kGhsStride;     // biases: [0,24) b_hh, [24,48) b_ih,
                                            // [48,72) w_ih, [72,80) p_b1,
                                            // [80,88) p_w2, [88] p_b2
  float* sxin = sb + 96;                    // [128] selected inputs

  const int tid = threadIdx.x;
  const int d = blockIdx.x >> 6;   // 0 = forward, 1 = backward
  const int c = blockIdx.x & 63;   // CTA index within direction
  const int j0 = c * kCols;        // base hidden column

  const float* w_hh = d ? wb_hh : wf_hh;
  const float* w_ih = d ? wb_ih : wf_ih;
  const float* b_hh = d ? bb_hh : bf_hh;
  const float* b_ih = d ? bb_ih : bf_ih;

  const int mmode = g_mask_mode;

  // ---- one-time weight staging ----
  // local rows 0..7: w_hh r-gate rows j0..j0+7 ; 8..15: z ; 16..23: n ;
  // 24..31: p_w1 rows j0..j0+7.
  for (int i = tid; i < kRows * kH; i += kThreads) {
    int r = i >> 9, k = i & (kH - 1);
    float v;
    if (r < 24)
      v = w_hh[((r >> 3) * kH + j0 + (r & 7)) * kH + k];
    else
      v = p_w1[(j0 + (r & 7)) * kH + k];
    ws[r * kWsStride + k] = v;
  }
  if (tid < 24) {
    int g = tid >> 3, jj = tid & 7;
    sb[tid] = b_hh[g * kH + j0 + jj];
    sb[24 + tid] = b_ih[g * kH + j0 + jj];
    sb[48 + tid] = w_ih[g * kH + j0 + jj];  // w_ih is (3H, 1)
  } else if (tid < 32) {
    int jj = tid - 24;
    sb[72 + jj] = p_b1[j0 + jj];
    sb[80 + jj] = p_w2[j0 + jj];
  } else if (tid == 32) {
    sb[88] = p_b2[0];
  }
  __syncthreads();

  // GEMM thread tile: 8 batches (4 f32x2 pairs) x 2 rows per thread.
  const int tr = tid >> 4, tc = tid & 15;
  const int b0 = tr * 8;
  const int r0 = tc * 2;

  int cur = 0;
  unsigned int phase = 0;

  for (int t = 0; t < kT; ++t) {
    const float* hsrc = &g_h[d][cur][0][0];

    // prefetch chunk 0 (h was written by other SMs -> .cg, bypass L1)
    float4 pref[8];
#pragma unroll
    for (int i = 0; i < 8; ++i)
      pref[i] = __ldcg(reinterpret_cast<const float4*>(hsrc) + i * kThreads + tid);

    unsigned long long acc[4][2];
#pragma unroll
    for (int p = 0; p < 4; ++p) {
      acc[p][0] = 0ull;
      acc[p][1] = 0ull;
    }

    // ---- Phase A: C = h @ Wslice^T over K=512 in chunks of 64 ----
    for (int kc = 0; kc < kNChunk; ++kc) {
      __syncthreads();  // hs free (previous chunk consumed)
#pragma unroll
      for (int i = 0; i < 8; ++i)
        reinterpret_cast<float4*>(hs)[i * kThreads + tid] = pref[i];
      __syncthreads();
      if (kc + 1 < kNChunk) {
        const float4* src4 =
            reinterpret_cast<const float4*>(hsrc + (kc + 1) * kChunk * kB);
#pragma unroll
        for (int i = 0; i < 8; ++i) pref[i] = __ldcg(src4 + i * kThreads + tid);
      }
      const float* hp0 = hs + b0;
      const float* wr0 = ws + r0 * kWsStride + kc * kChunk;
      const float* wr1 = wr0 + kWsStride;
#pragma unroll 8
      for (int k = 0; k < kChunk; ++k) {
        ulonglong2 aA = *reinterpret_cast<const ulonglong2*>(hp0 + k * kB);
        ulonglong2 aB = *reinterpret_cast<const ulonglong2*>(hp0 + k * kB + 4);
        unsigned long long w0 = pk2(wr0[k]);
        unsigned long long w1 = pk2(wr1[k]);
        fma2(acc[0][0], aA.x, w0);
        fma2(acc[1][0], aA.y, w0);
        fma2(acc[2][0], aB.x, w0);
        fma2(acc[3][0], aB.y, w0);
        fma2(acc[0][1], aA.x, w1);
        fma2(acc[1][1], aA.y, w1);
        fma2(acc[2][1], aB.x, w1);
        fma2(acc[3][1], aB.y, w1);
      }
    }

    // ---- Phase A epilogue: gh rows get +b_hh; predictor rows get
    //      relu(u + p_b1) * p_w2 (ready for the scalar reduction).
#pragma unroll
    for (int rr = 0; rr < 2; ++rr) {
      int row = r0 + rr;
      if (row < 24) {
        float bb = sb[row];
#pragma unroll
        for (int p = 0; p < 4; ++p) {
          float2 v = unpk(acc[p][rr]);
          ghs[row * kGhsStride + b0 + 2 * p] = v.x + bb;
          ghs[row * kGhsStride + b0 + 2 * p + 1] = v.y + bb;
        }
      } else {
        int jj = row - 24;
        float b1v = sb[72 + jj], w2v = sb[80 + jj];
#pragma unroll
        for (int p = 0; p < 4; ++p) {
          float2 v = unpk(acc[p][rr]);
          ghs[row * kGhsStride + b0 + 2 * p] = fmaxf(v.x + b1v, 0.f) * w2v;
          ghs[row * kGhsStride + b0 + 2 * p + 1] = fmaxf(v.y + b1v, 0.f) * w2v;
        }
      }
    }
    __syncthreads();
    if (tid < kB) {
      float sp = 0.f;
#pragma unroll
      for (int r = 24; r < 32; ++r) sp += ghs[r * kGhsStride + tid];
      __stcg(&g_spart[d][tid][c], sp);
    }
    group_barrier(d, ++phase, c);

    const int pos = d ? (kT - 1 - t) : t;

    // ---- Phase B: predictor scalar + input select ----
    if (tid < kB) {
      float a = sb[88];  // p_b2
      const float4* pp = reinterpret_cast<const float4*>(&g_spart[d][tid][0]);
#pragma unroll
      for (int q = 0; q < kCtaPerDir / 4; ++q) {
        float4 v = __ldcg(pp + q);
        a += v.x + v.y + v.z + v.w;
      }
      float s = tanh_fast(a);
      float xv = __ldg(&x[tid * kT + pos]);
      const int midx = tid * kT + pos;
      bool m;
      if (mmode == 1)
        m = ((const int*)mask)[midx] != 0;
      else if (mmode == 2)
        m = ((const float*)mask)[midx] != 0.f;
      else
        m = ((const uint8_t*)mask)[midx] != 0;
      sxin[tid] = m ? s : xv;
    }
    __syncthreads();

    // ---- Phase B: gates + state update + output ----
    const int nxt = cur ^ 1;
#pragma unroll
    for (int i = tid; i < kB * kCols; i += kThreads) {
      int b = i >> 3, jj = i & 7;
      float xin = sxin[b];
      float gr = ghs[jj * kGhsStride + b] + fmaf(xin, sb[48 + jj], sb[24 + jj]);
      float gz = ghs[(8 + jj) * kGhsStride + b] +
                 fmaf(xin, sb[48 + 8 + jj], sb[24 + 8 + jj]);
      float ghn = ghs[(16 + jj) * kGhsStride + b];
      float gin = fmaf(xin, sb[48 + 16 + jj], sb[24 + 16 + jj]);
      float r = sigmoid_fast(gr);
      float z = sigmoid_fast(gz);
      float n = tanh_fast(fmaf(r, ghn, gin));
      float hold = __ldcg(&g_h[d][cur][j0 + jj][b]);
      float hnew = fmaf(z, hold - n, n);  // (1-z)*n + z*h
      __stcg(&g_h[d][nxt][j0 + jj][b], hnew);
      out[(size_t)b * (kT * 2 * kH) + (size_t)pos * (2 * kH) + d * kH + j0 + jj] =
          hnew;
    }
    group_barrier(d, ++phase, c);
    cur = nxt;
  }
}

extern "C" void kernel_launch(void* const* d_in, const int* in_sizes, int n_in,
                              void* d_out, int out_size) {
  const float* x = (const float*)d_in[0];
  const void* mask = (const void*)d_in[1];
  const float* wf_ih = (const float*)d_in[2];
  const float* wf_hh = (const float*)d_in[3];
  const float* bf_ih = (const float*)d_in[4];
  const float* bf_hh = (const float*)d_in[5];
  const float* wb_ih = (const float*)d_in[6];
  const float* wb_hh = (const float*)d_in[7];
  const float* bb_ih = (const float*)d_in[8];
  const float* bb_hh = (const float*)d_in[9];
  const float* p_w1 = (const float*)d_in[10];
  const float* p_b1 = (const float*)d_in[11];
  const float* p_w2 = (const float*)d_in[12];
  const float* p_b2 = (const float*)d_in[13];
  float* out = (float*)d_out;

  (void)in_sizes;
  (void)n_in;
  (void)out_size;

  cudaFuncSetAttribute(bidgru_kernel, cudaFuncAttributeMaxDynamicSharedMemorySize,
                       kSmemBytes);
  init_kernel<<<256, 256>>>(mask);
  bidgru_kernel<<<kNCta, kThreads, kSmemBytes>>>(x, mask, wf_ih, wf_hh, bf_ih, bf_hh,
                                                 wb_ih, wb_hh, bb_ih, bb_hh, p_w1,
                                                 p_b1, p_w2, p_b2, out);
}

// round 6
// speedup vs baseline: 1.5440x; 1.5440x over previous
#include <cuda_runtime.h>
#include <cuda_bf16.h>
#include <stdint.h>

// ---------------------------------------------------------------------------
// Bidirectional GRU w/ predictor feedback. B=128, T=1024, H=512.
// Persistent grid: 128 CTAs (64/dir), 256 thr, ~218KB SMEM (1 CTA/SM).
// Per step, CTA c of dir d computes C[128b x 32n] = h[128x512] @ W[32x512]^T
// with mma.sync m16n8k16 bf16 (hi/lo split, 3 products -> fp32-class
// precision). W rows 0..23 = gh (r,z,n gates x 8 cols), 24..31 = p_w1 rows.
// Warps 0-3: MMA (2 M-tiles each). Warps 4-7: stage h K-chunks gmem->SMEM
// (double buffered). h state fp32 in registers of thread b (tid<128),
// published as bf16 hi+lo to gmem for the next step's A operand.
// NOTE: harness emits compute_103 PTX (no 'a') -> tcgen05/TMA-tensor are
// unavailable; mma.sync is the fastest legal tensor path.
// R6 fix: A-staging loop now loads the FULL 128-wide K chunk (i<32, q&15);
// R5 loaded only the lower 64 k of each chunk (rel_err 0.21).
// ---------------------------------------------------------------------------

namespace {
constexpr int kB = 128;
constexpr int kT = 1024;
constexpr int kH = 512;
constexpr int kCtaPerDir = 64;
constexpr int kNCta = 2 * kCtaPerDir;
constexpr int kThreads = 256;
constexpr int kCols = 8;

// SMEM layout (byte offsets). Strides chosen so word-stride % 32 == 4
// (conflict-free fragment loads).
constexpr int kWStride = 520;                     // bf16 units per W row (512+8)
constexpr int kWPart = 32 * kWStride * 2;         // 33280 B
constexpr int kWHi = 0;
constexpr int kWLo = kWPart;                      // 33280
constexpr int kABase = 2 * kWPart;                // 66560
constexpr int kAStride = 136;                     // bf16 units per A row (128+8)
constexpr int kAPart = kB * kAStride * 2;         // 34816 B
constexpr int kGhs = kABase + 4 * kAPart;         // 205824 ([32][132] f32)
constexpr int kGhsStride = 132;                   // words
constexpr int kSb = kGhs + 32 * kGhsStride * 4;   // 222720 (96 f32 biases)
constexpr int kSmemBytes = 223232;
}  // namespace

// Device-global scratch (no allocation allowed).
__device__ __align__(16) __nv_bfloat16 g_hb[2][2][2][kB][kH];  // [dir][buf][part][b][k]
__device__ float g_spart[2][kB][kCtaPerDir];
__device__ unsigned int g_flags[2][kCtaPerDir * 8];
__device__ int g_mask_mode;  // 0=u8, 1=i32, 2=f32

__device__ __forceinline__ float sigmoid_fast(float v) {
  return __fdividef(1.f, 1.f + __expf(-v));
}
__device__ __forceinline__ float tanh_fast(float v) {
  return 1.f - __fdividef(2.f, 1.f + __expf(2.f * v));
}

// m16n8k16 row.col f32.bf16.bf16.f32
__device__ __forceinline__ void mma16816(float* d, uint32_t a0, uint32_t a1,
                                         uint32_t a2, uint32_t a3, uint32_t b0,
                                         uint32_t b1) {
  asm volatile(
      "mma.sync.aligned.m16n8k16.row.col.f32.bf16.bf16.f32 "
      "{%0,%1,%2,%3},{%4,%5,%6,%7},{%8,%9},{%0,%1,%2,%3};"
      : "+f"(d[0]), "+f"(d[1]), "+f"(d[2]), "+f"(d[3])
      : "r"(a0), "r"(a1), "r"(a2), "r"(a3), "r"(b0), "r"(b1));
}

// Per-direction grid barrier (proven in R2). 64 co-resident CTAs per dir.
__device__ __forceinline__ void group_barrier(int d, unsigned int phase, int c) {
  __syncthreads();
  if (threadIdx.x == 0) {
    asm volatile("st.release.gpu.u32 [%0], %1;" ::"l"(&g_flags[d][c * 8]),
                 "r"(phase)
                 : "memory");
  }
  if (threadIdx.x < kCtaPerDir) {
    const unsigned int* fp = &g_flags[d][threadIdx.x * 8];
    unsigned int v;
    do {
      asm volatile("ld.acquire.gpu.u32 %0, [%1];" : "=r"(v) : "l"(fp) : "memory");
    } while (v < phase);
  }
  __syncthreads();
}

__global__ void init_kernel(const void* __restrict__ mask) {
  int idx = blockIdx.x * blockDim.x + threadIdx.x;  // 65536 threads
  reinterpret_cast<uint4*>(&g_hb[0][0][0][0][0])[idx] = make_uint4(0, 0, 0, 0);
  if (idx < 2 * kCtaPerDir * 8) (&g_flags[0][0])[idx] = 0u;
  if (idx == 0) {
    const int* i32 = (const int*)mask;
    const float* f32 = (const float*)mask;
    bool is_i32 = true, is_f32 = true;
    for (int i = 0; i < 64; ++i) {
      int v = i32[i];
      if (v != 0 && v != 1) is_i32 = false;
      float f = f32[i];
      if (!(f == 0.f || f == 1.f)) is_f32 = false;
    }
    g_mask_mode = is_i32 ? 1 : (is_f32 ? 2 : 0);
  }
}

__global__ void __launch_bounds__(kThreads, 1)
bidgru_kernel(const float* __restrict__ x, const void* __restrict__ mask,
              const float* __restrict__ wf_ih, const float* __restrict__ wf_hh,
              const float* __restrict__ bf_ih, const float* __restrict__ bf_hh,
              const float* __restrict__ wb_ih, const float* __restrict__ wb_hh,
              const float* __restrict__ bb_ih, const float* __restrict__ bb_hh,
              const float* __restrict__ p_w1, const float* __restrict__ p_b1,
              const float* __restrict__ p_w2, const float* __restrict__ p_b2,
              float* __restrict__ out) {
  extern __shared__ __align__(16) char smem_c[];
  float* sb = reinterpret_cast<float*>(smem_c + kSb);
  float* ghs = reinterpret_cast<float*>(smem_c + kGhs);
  uint32_t* Wh = reinterpret_cast<uint32_t*>(smem_c + kWHi);
  uint32_t* Wl = reinterpret_cast<uint32_t*>(smem_c + kWLo);

  const int tid = threadIdx.x;
  const int wid = tid >> 5;
  const int lane = tid & 31;
  const int d = blockIdx.x >> 6;
  const int c = blockIdx.x & 63;
  const int j0 = c * kCols;

  const float* w_hh = d ? wb_hh : wf_hh;
  const float* w_ih = d ? wb_ih : wf_ih;
  const float* b_hh = d ? bb_hh : bf_hh;
  const float* b_ih = d ? bb_ih : bf_ih;
  const int mmode = g_mask_mode;

  // ---- one-time W staging: fp32 -> bf16 hi/lo, rows [n][k] stride 520 ----
  // n 0..7: r-gate cols j0..j0+7 ; 8..15: z ; 16..23: n-gate ; 24..31: p_w1.
  for (int i = tid; i < 32 * kH; i += kThreads) {
    int r = i >> 9, k = i & (kH - 1);
    float v = (r < 24) ? w_hh[((r >> 3) * kH + j0 + (r & 7)) * kH + k]
                       : p_w1[(j0 + (r & 7)) * kH + k];
    __nv_bfloat16 hi = __float2bfloat16_rn(v);
    __nv_bfloat16 lo = __float2bfloat16_rn(v - __bfloat162float(hi));
    reinterpret_cast<unsigned short*>(smem_c + kWHi)[r * kWStride + k] =
        __bfloat16_as_ushort(hi);
    reinterpret_cast<unsigned short*>(smem_c + kWLo)[r * kWStride + k] =
        __bfloat16_as_ushort(lo);
  }
  if (tid < 24) {
    int g = tid >> 3, jj = tid & 7;
    sb[tid] = b_hh[g * kH + j0 + jj];
    sb[24 + tid] = b_ih[g * kH + j0 + jj];
    sb[48 + tid] = w_ih[g * kH + j0 + jj];
  } else if (tid < 32) {
    int jj = tid - 24;
    sb[72 + jj] = p_b1[j0 + jj];
    sb[80 + jj] = p_w2[j0 + jj];
  } else if (tid == 32) {
    sb[88] = p_b2[0];
  }
  __syncthreads();

  // fragment lane coords
  const int r0q = lane >> 2;   // row within 8-group
  const int cq = lane & 3;     // k/col quad

  // persistent fp32 hidden state: thread b (=tid<128) owns h[b][j0..j0+8)
  float hreg[kCols];
#pragma unroll
  for (int jj = 0; jj < kCols; ++jj) hreg[jj] = 0.f;

  int cur = 0;
  unsigned int gphase = 0;

  for (int t = 0; t < kT; ++t) {
    const uint4* hb4 = reinterpret_cast<const uint4*>(&g_hb[d][cur][0][0][0]);

    float acc[2][4][4];
#pragma unroll
    for (int mt = 0; mt < 2; ++mt)
#pragma unroll
      for (int nt = 0; nt < 4; ++nt)
#pragma unroll
        for (int q = 0; q < 4; ++q) acc[mt][nt][q] = 0.f;

    // ---- pipelined: stage chunk kc (warps 4-7) / mma chunk kc-1 (warps 0-3)
    for (int kc = 0; kc < 5; ++kc) {
      __syncthreads();
      if (tid >= 128) {
        if (kc < 4) {
          const int buf = kc & 1;
          const int t1 = tid - 128;
          // full chunk: 2 parts x 128 b-rows x 16 uint4 (128 k) = 4096 uint4
#pragma unroll
          for (int i = 0; i < 32; ++i) {
            int u = i * 128 + t1;
            int p = u >> 11, rem = u & 2047;
            int b = rem >> 4, q = rem & 15;
            uint4 v = __ldcg(hb4 + (p * kB + b) * 64 + kc * 16 + q);
            *reinterpret_cast<uint4*>(smem_c + kABase + (buf * 2 + p) * kAPart +
                                      b * 272 + q * 16) = v;
          }
        }
      } else if (kc > 0) {
        const int cc = kc - 1;
        const int buf = cc & 1;
        const uint32_t* Ah =
            reinterpret_cast<const uint32_t*>(smem_c + kABase + (buf * 2) * kAPart);
        const uint32_t* Al = reinterpret_cast<const uint32_t*>(
            smem_c + kABase + (buf * 2 + 1) * kAPart);
#pragma unroll
        for (int ks = 0; ks < 8; ++ks) {
          // B frags for all 4 n-tiles, hi & lo.  word = n*260 + kglob*8 + cq
          uint32_t bh[4][2], bl[4][2];
          const int bw = r0q * 260 + (cc * 8 + ks) * 8 + cq;
#pragma unroll
          for (int nt = 0; nt < 4; ++nt) {
            bh[nt][0] = Wh[bw + nt * 2080];
            bh[nt][1] = Wh[bw + nt * 2080 + 4];
            bl[nt][0] = Wl[bw + nt * 2080];
            bl[nt][1] = Wl[bw + nt * 2080 + 4];
          }
#pragma unroll
          for (int mt = 0; mt < 2; ++mt) {
            const int row = (2 * wid + mt) * 16 + r0q;
            const int aw = row * 68 + ks * 8 + cq;
            uint32_t ah0 = Ah[aw], ah1 = Ah[aw + 544], ah2 = Ah[aw + 4],
                     ah3 = Ah[aw + 548];
            uint32_t al0 = Al[aw], al1 = Al[aw + 544], al2 = Al[aw + 4],
                     al3 = Al[aw + 548];
#pragma unroll
            for (int nt = 0; nt < 4; ++nt) {
              mma16816(acc[mt][nt], ah0, ah1, ah2, ah3, bh[nt][0], bh[nt][1]);
              mma16816(acc[mt][nt], al0, al1, al2, al3, bh[nt][0], bh[nt][1]);
              mma16816(acc[mt][nt], ah0, ah1, ah2, ah3, bl[nt][0], bl[nt][1]);
            }
          }
        }
      }
    }

    // ---- write C to ghs [n][b] (stride 132 words, conflict-free) ----
    if (tid < 128) {
#pragma unroll
      for (int mt = 0; mt < 2; ++mt) {
        const int br = (2 * wid + mt) * 16 + r0q;
#pragma unroll
        for (int nt = 0; nt < 4; ++nt) {
          const int n0 = nt * 8 + cq * 2;
          ghs[n0 * kGhsStride + br] = acc[mt][nt][0];
          ghs[(n0 + 1) * kGhsStride + br] = acc[mt][nt][1];
          ghs[n0 * kGhsStride + br + 8] = acc[mt][nt][2];
          ghs[(n0 + 1) * kGhsStride + br + 8] = acc[mt][nt][3];
        }
      }
    }
    __syncthreads();

    const int pos = d ? (kT - 1 - t) : t;
    const int nxt = cur ^ 1;

    float xv = 0.f;
    bool m = false;
    if (tid < kB) {
      const int b = tid;
      // predictor partial for this CTA's 8 p_w1 rows
      float sp = 0.f;
#pragma unroll
      for (int jj = 0; jj < 8; ++jj)
        sp += fmaxf(ghs[(24 + jj) * kGhsStride + b] + sb[72 + jj], 0.f) *
              sb[80 + jj];
      __stcg(&g_spart[d][b][c], sp);
      // independent loads overlapped with the barrier
      xv = __ldg(&x[(size_t)b * kT + pos]);
      const size_t midx = (size_t)b * kT + pos;
      if (mmode == 1)
        m = ((const int*)mask)[midx] != 0;
      else if (mmode == 2)
        m = ((const float*)mask)[midx] != 0.f;
      else
        m = ((const uint8_t*)mask)[midx] != 0;
    }
    group_barrier(d, ++gphase, c);

    if (tid < kB) {
      const int b = tid;
      float a = sb[88];
      const float4* pp = reinterpret_cast<const float4*>(&g_spart[d][b][0]);
#pragma unroll
      for (int q = 0; q < kCtaPerDir / 4; ++q) {
        float4 v = __ldcg(pp + q);
        a += v.x + v.y + v.z + v.w;
      }
      float s = tanh_fast(a);
      float xin = m ? s : xv;

      unsigned short hi16[kCols], lo16[kCols];
      float onew[kCols];
#pragma unroll
      for (int jj = 0; jj < kCols; ++jj) {
        float gr = ghs[jj * kGhsStride + b] + sb[jj] +
                   fmaf(xin, sb[48 + jj], sb[24 + jj]);
        float gz = ghs[(8 + jj) * kGhsStride + b] + sb[8 + jj] +
                   fmaf(xin, sb[48 + 8 + jj], sb[24 + 8 + jj]);
        float ghn = ghs[(16 + jj) * kGhsStride + b] + sb[16 + jj];
        float gin = fmaf(xin, sb[48 + 16 + jj], sb[24 + 16 + jj]);
        float r = sigmoid_fast(gr);
        float z = sigmoid_fast(gz);
        float n = tanh_fast(fmaf(r, ghn, gin));
        float hnew = fmaf(z, hreg[jj] - n, n);
        hreg[jj] = hnew;
        onew[jj] = hnew;
        __nv_bfloat16 h_hi = __float2bfloat16_rn(hnew);
        __nv_bfloat16 h_lo = __float2bfloat16_rn(hnew - __bfloat162float(h_hi));
        hi16[jj] = __bfloat16_as_ushort(h_hi);
        lo16[jj] = __bfloat16_as_ushort(h_lo);
      }
      uint4 vhi, vlo;
      vhi.x = (uint32_t)hi16[0] | ((uint32_t)hi16[1] << 16);
      vhi.y = (uint32_t)hi16[2] | ((uint32_t)hi16[3] << 16);
      vhi.z = (uint32_t)hi16[4] | ((uint32_t)hi16[5] << 16);
      vhi.w = (uint32_t)hi16[6] | ((uint32_t)hi16[7] << 16);
      vlo.x = (uint32_t)lo16[0] | ((uint32_t)lo16[1] << 16);
      vlo.y = (uint32_t)lo16[2] | ((uint32_t)lo16[3] << 16);
      vlo.z = (uint32_t)lo16[4] | ((uint32_t)lo16[5] << 16);
      vlo.w = (uint32_t)lo16[6] | ((uint32_t)lo16[7] << 16);
      __stcg(reinterpret_cast<uint4*>(&g_hb[d][nxt][0][b][j0]), vhi);
      __stcg(reinterpret_cast<uint4*>(&g_hb[d][nxt][1][b][j0]), vlo);
      float* op = out + ((size_t)b << 20) + ((size_t)pos << 10) + (d << 9) + j0;
      *reinterpret_cast<float4*>(op) =
          make_float4(onew[0], onew[1], onew[2], onew[3]);
      *reinterpret_cast<float4*>(op + 4) =
          make_float4(onew[4], onew[5], onew[6], onew[7]);
    }
    group_barrier(d, ++gphase, c);
    cur = nxt;
  }
}

extern "C" void kernel_launch(void* const* d_in, const int* in_sizes, int n_in,
                              void* d_out, int out_size) {
  const float* x = (const float*)d_in[0];
  const void* mask = (const void*)d_in[1];
  const float* wf_ih = (const float*)d_in[2];
  const float* wf_hh = (const float*)d_in[3];
  const float* bf_ih = (const float*)d_in[4];
  const float* bf_hh = (const float*)d_in[5];
  const float* wb_ih = (const float*)d_in[6];
  const float* wb_hh = (const float*)d_in[7];
  const float* bb_ih = (const float*)d_in[8];
  const float* bb_hh = (const float*)d_in[9];
  const float* p_w1 = (const float*)d_in[10];
  const float* p_b1 = (const float*)d_in[11];
  const float* p_w2 = (const float*)d_in[12];
  const float* p_b2 = (const float*)d_in[13];
  float* out = (float*)d_out;

  (void)in_sizes;
  (void)n_in;
  (void)out_size;

  cudaFuncSetAttribute(bidgru_kernel, cudaFuncAttributeMaxDynamicSharedMemorySize,
                       kSmemBytes);
  init_kernel<<<256, 256>>>(mask);
  bidgru_kernel<<<kNCta, kThreads, kSmemBytes>>>(x, mask, wf_ih, wf_hh, bf_ih,
                                                 bf_hh, wb_ih, wb_hh, bb_ih, bb_hh,
                                                 p_w1, p_b1, p_w2, p_b2, out);
}

// round 7
// speedup vs baseline: 1.7790x; 1.1522x over previous
#include <cuda_runtime.h>
#include <cuda_bf16.h>
#include <stdint.h>

// ---------------------------------------------------------------------------
// Bidirectional GRU w/ predictor feedback. B=128, T=1024, H=512.
// Persistent grid: 128 CTAs (64/dir), 384 thr, ~214KB SMEM (1 CTA/SM).
// Per step, CTA c of dir d computes C[128b x 32n] = h[128x512] @ W[32x512]^T
// with mma.sync m16n8k16 bf16 (hi/lo split, 3 products). Fragments via
// ldmatrix.x4. Warps 0-3: MMA (2 m-tiles x 4 n-tiles). Warps 4-11: stage h
// K-chunks gmem->SMEM, double buffered, decoupled from MMA via named
// barriers (full/empty). Predictor partials come straight from MMA
// accumulators via butterfly shuffles. Epilogue on 256 threads (4 cols each).
// Grid-barrier arrivals are issued early so the flag propagates under
// independent work (x/mask loads, out stores).
// ---------------------------------------------------------------------------

namespace {
constexpr int kB = 128;
constexpr int kT = 1024;
constexpr int kH = 512;
constexpr int kCtaPerDir = 64;
constexpr int kNCta = 2 * kCtaPerDir;
constexpr int kThreads = 384;

// SMEM layout (byte offsets). Word strides % 32 == 4 -> conflict-free.
constexpr int kWStride = 520;                    // bf16 per W row (512+8)
constexpr int kWPart = 32 * kWStride * 2;        // 33280 B
constexpr int kWHi = 0;
constexpr int kWLo = kWPart;                     // 33280
constexpr int kABase = 2 * kWPart;               // 66560
constexpr int kARow = 272;                       // bytes per A row (128k bf16 + pad)
constexpr int kAPart = kB * kARow;               // 34816 B
constexpr int kGhs = kABase + 4 * kAPart;        // 205824 ([24][132] f32)
constexpr int kGhsStride = 132;                  // words
constexpr int kSb = kGhs + 24 * kGhsStride * 4;  // 218496 (96 f32 biases)
constexpr int kSmemBytes = 219136;               // > 114KB -> 1 CTA/SM
}  // namespace

// Device-global scratch (no allocation allowed).
__device__ __align__(16) __nv_bfloat16 g_hb[2][2][2][kB][kH];  // [dir][buf][part][b][k]
__device__ float g_spart[2][kB][kCtaPerDir];
__device__ unsigned int g_flags[2][kCtaPerDir * 8];
__device__ int g_mask_mode;  // 0=u8, 1=i32, 2=f32

__device__ __forceinline__ float sigmoid_fast(float v) {
  return __fdividef(1.f, 1.f + __expf(-v));
}
__device__ __forceinline__ float tanh_fast(float v) {
  return 1.f - __fdividef(2.f, 1.f + __expf(2.f * v));
}

__device__ __forceinline__ uint32_t smem_u32(const void* p) {
  uint32_t a;
  asm("{ .reg .u64 t; cvta.to.shared.u64 t, %1; cvt.u32.u64 %0, t; }"
      : "=r"(a) : "l"(p));
  return a;
}

// m16n8k16 row.col f32.bf16.bf16.f32
__device__ __forceinline__ void mma16816(float* d, uint32_t a0, uint32_t a1,
                                         uint32_t a2, uint32_t a3, uint32_t b0,
                                         uint32_t b1) {
  asm volatile(
      "mma.sync.aligned.m16n8k16.row.col.f32.bf16.bf16.f32 "
      "{%0,%1,%2,%3},{%4,%5,%6,%7},{%8,%9},{%0,%1,%2,%3};"
      : "+f"(d[0]), "+f"(d[1]), "+f"(d[2]), "+f"(d[3])
      : "r"(a0), "r"(a1), "r"(a2), "r"(a3), "r"(b0), "r"(b1));
}

#define LDM4(r, addr)                                                        \
  asm volatile(                                                              \
      "ldmatrix.sync.aligned.m8n8.x4.shared.b16 {%0,%1,%2,%3}, [%4];"        \
      : "=r"((r)[0]), "=r"((r)[1]), "=r"((r)[2]), "=r"((r)[3])               \
      : "r"(addr))

__device__ __forceinline__ void barx_sync(int id) {
  asm volatile("bar.sync %0, %1;" ::"r"(id), "r"(kThreads) : "memory");
}
__device__ __forceinline__ void barx_arrive(int id) {
  asm volatile("bar.arrive %0, %1;" ::"r"(id), "r"(kThreads) : "memory");
}

// Split grid barrier: early arrive, late wait (poll by tid<64).
__device__ __forceinline__ void gb_arrive(int d, unsigned int phase, int c) {
  asm volatile("st.release.gpu.u32 [%0], %1;" ::"l"(&g_flags[d][c * 8]),
               "r"(phase)
               : "memory");
}
__device__ __forceinline__ void gb_wait(int d, unsigned int phase, int tid) {
  if (tid < kCtaPerDir) {
    const unsigned int* fp = &g_flags[d][tid * 8];
    unsigned int v;
    do {
      asm volatile("ld.acquire.gpu.u32 %0, [%1];" : "=r"(v) : "l"(fp) : "memory");
    } while (v < phase);
  }
}

__global__ void init_kernel(const void* __restrict__ mask) {
  int idx = blockIdx.x * blockDim.x + threadIdx.x;  // 65536 threads
  reinterpret_cast<uint4*>(&g_hb[0][0][0][0][0])[idx] = make_uint4(0, 0, 0, 0);
  if (idx < 2 * kCtaPerDir * 8) (&g_flags[0][0])[idx] = 0u;
  if (idx == 0) {
    const int* i32 = (const int*)mask;
    const float* f32 = (const float*)mask;
    bool is_i32 = true, is_f32 = true;
    for (int i = 0; i < 64; ++i) {
      int v = i32[i];
      if (v != 0 && v != 1) is_i32 = false;
      float f = f32[i];
      if (!(f == 0.f || f == 1.f)) is_f32 = false;
    }
    g_mask_mode = is_i32 ? 1 : (is_f32 ? 2 : 0);
  }
}

__global__ void __launch_bounds__(kThreads, 1)
bidgru_kernel(const float* __restrict__ x, const void* __restrict__ mask,
              const float* __restrict__ wf_ih, const float* __restrict__ wf_hh,
              const float* __restrict__ bf_ih, const float* __restrict__ bf_hh,
              const float* __restrict__ wb_ih, const float* __restrict__ wb_hh,
              const float* __restrict__ bb_ih, const float* __restrict__ bb_hh,
              const float* __restrict__ p_w1, const float* __restrict__ p_b1,
              const float* __restrict__ p_w2, const float* __restrict__ p_b2,
              float* __restrict__ out) {
  extern __shared__ __align__(16) char smem_c[];
  const uint32_t smem_base = smem_u32(smem_c);
  float* sb = reinterpret_cast<float*>(smem_c + kSb);
  float* ghs = reinterpret_cast<float*>(smem_c + kGhs);

  const int tid = threadIdx.x;
  const int wid = tid >> 5;
  const int lane = tid & 31;
  const int d = blockIdx.x >> 6;
  const int c = blockIdx.x & 63;
  const int j0 = c * 8;

  const float* w_hh = d ? wb_hh : wf_hh;
  const float* w_ih = d ? wb_ih : wf_ih;
  const float* b_hh = d ? bb_hh : bf_hh;
  const float* b_ih = d ? bb_ih : bf_ih;
  const int mmode = g_mask_mode;

  // ---- one-time W staging: fp32 -> bf16 hi/lo, rows [n][k] stride 520 ----
  for (int i = tid; i < 32 * kH; i += kThreads) {
    int r = i >> 9, k = i & (kH - 1);
    float v = (r < 24) ? w_hh[((r >> 3) * kH + j0 + (r & 7)) * kH + k]
                       : p_w1[(j0 + (r & 7)) * kH + k];
    __nv_bfloat16 hi = __float2bfloat16_rn(v);
    __nv_bfloat16 lo = __float2bfloat16_rn(v - __bfloat162float(hi));
    reinterpret_cast<unsigned short*>(smem_c + kWHi)[r * kWStride + k] =
        __bfloat16_as_ushort(hi);
    reinterpret_cast<unsigned short*>(smem_c + kWLo)[r * kWStride + k] =
        __bfloat16_as_ushort(lo);
  }
  if (tid < 24) {
    int g = tid >> 3, jj = tid & 7;
    sb[tid] = b_hh[g * kH + j0 + jj];
    sb[24 + tid] = b_ih[g * kH + j0 + jj];
    sb[48 + tid] = w_ih[g * kH + j0 + jj];
  } else if (tid < 32) {
    int jj = tid - 24;
    sb[72 + jj] = p_b1[j0 + jj];
    sb[80 + jj] = p_w2[j0 + jj];
  } else if (tid == 32) {
    sb[88] = p_b2[0];
  }
  __syncthreads();

  const bool is_mma = tid < 128;
  const int r0q = lane >> 2, cq = lane & 3;
  const int md = lane >> 3, mr = lane & 7;
  // ldmatrix per-lane byte offsets
  const uint32_t a_off = (uint32_t)(((md & 1) * 8 + mr) * kARow + (md >> 1) * 16);
  const uint32_t b_off =
      (uint32_t)((((md >> 1) * 8 + mr) * kWStride) * 2 + (md & 1) * 16);
  const uint32_t wh_addr = smem_base + kWHi;
  const uint32_t wl_addr = smem_base + kWLo;

  // epilogue geometry: thread (eb, ehalf) owns h[eb][j0 + ehalf*4 .. +4)
  const int eb = tid >> 1, ehalf = tid & 1;
  float hreg[4] = {0.f, 0.f, 0.f, 0.f};

  int cur = 0;
  unsigned int gphase = 0;

  for (int t = 0; t < kT; ++t) {
    const uint4* hb4 = reinterpret_cast<const uint4*>(&g_hb[d][cur][0][0][0]);

    float acc[2][4][4];
#pragma unroll
    for (int mt = 0; mt < 2; ++mt)
#pragma unroll
      for (int nt = 0; nt < 4; ++nt)
#pragma unroll
        for (int q = 0; q < 4; ++q) acc[mt][nt][q] = 0.f;

    // ---- Phase A: producer/consumer over 4 K-chunks, double buffered ----
    for (int kc = 0; kc < 4; ++kc) {
      const int buf = kc & 1;
      if (!is_mma) {
        if (!(t == 0 && kc < 2)) barx_sync(3 + buf);  // buffer empty?
        const int t1 = tid - 128;
#pragma unroll
        for (int i = 0; i < 16; ++i) {
          int u = i * 256 + t1;
          int p = u >> 11, rem = u & 2047;
          int b = rem >> 4, q = rem & 15;
          uint4 v = __ldcg(hb4 + (p * kB + b) * 64 + kc * 16 + q);
          *reinterpret_cast<uint4*>(smem_c + kABase + (buf * 2 + p) * kAPart +
                                    b * kARow + q * 16) = v;
        }
        barx_arrive(1 + buf);  // buffer full
      } else {
        barx_sync(1 + buf);  // wait buffer full
        const uint32_t ab_hi = smem_base + kABase + (buf * 2) * kAPart;
        const uint32_t ab_lo = ab_hi + kAPart;
        const uint32_t bko = (uint32_t)(kc * 256);
#pragma unroll
        for (int ks = 0; ks < 8; ++ks) {
          uint32_t ah[2][4], al[2][4];
#pragma unroll
          for (int mt = 0; mt < 2; ++mt) {
            uint32_t ao = a_off + (uint32_t)((2 * wid + mt) * 16 * kARow + ks * 32);
            LDM4(ah[mt], ab_hi + ao);
            LDM4(al[mt], ab_lo + ao);
          }
#pragma unroll
          for (int np = 0; np < 2; ++np) {
            uint32_t bh[4], bl[4];
            uint32_t bo = b_off + (uint32_t)(np * 16 * kWStride * 2) + bko +
                          (uint32_t)(ks * 32);
            LDM4(bh, wh_addr + bo);
            LDM4(bl, wl_addr + bo);
#pragma unroll
            for (int nti = 0; nti < 2; ++nti) {
              const int nt = np * 2 + nti;
              uint32_t B0 = bh[nti * 2], B1 = bh[nti * 2 + 1];
              uint32_t L0 = bl[nti * 2], L1 = bl[nti * 2 + 1];
#pragma unroll
              for (int mt = 0; mt < 2; ++mt) {
                mma16816(acc[mt][nt], ah[mt][0], ah[mt][1], ah[mt][2], ah[mt][3],
                         B0, B1);
                mma16816(acc[mt][nt], al[mt][0], al[mt][1], al[mt][2], al[mt][3],
                         B0, B1);
                mma16816(acc[mt][nt], ah[mt][0], ah[mt][1], ah[mt][2], ah[mt][3],
                         L0, L1);
              }
            }
          }
        }
        barx_arrive(3 + buf);  // buffer empty
      }
    }

    // ---- epilogue prologue: ghs scatter (gates) + spart from accumulators --
    if (is_mma) {
#pragma unroll
      for (int mt = 0; mt < 2; ++mt) {
        const int br = (2 * wid + mt) * 16 + r0q;
#pragma unroll
        for (int nt = 0; nt < 3; ++nt) {
          const int n0 = nt * 8 + cq * 2;
          ghs[n0 * kGhsStride + br] = acc[mt][nt][0];
          ghs[(n0 + 1) * kGhsStride + br] = acc[mt][nt][1];
          ghs[n0 * kGhsStride + br + 8] = acc[mt][nt][2];
          ghs[(n0 + 1) * kGhsStride + br + 8] = acc[mt][nt][3];
        }
      }
      // predictor partial: f(C[b, 24+jj]) summed over jj, via 2 bfly shuffles
      const float b1a = sb[72 + 2 * cq], b1b = sb[72 + 2 * cq + 1];
      const float w2a = sb[80 + 2 * cq], w2b = sb[80 + 2 * cq + 1];
#pragma unroll
      for (int mt = 0; mt < 2; ++mt) {
        float glo = fmaxf(acc[mt][3][0] + b1a, 0.f) * w2a +
                    fmaxf(acc[mt][3][1] + b1b, 0.f) * w2b;
        float ghi = fmaxf(acc[mt][3][2] + b1a, 0.f) * w2a +
                    fmaxf(acc[mt][3][3] + b1b, 0.f) * w2b;
        glo += __shfl_xor_sync(0xFFFFFFFFu, glo, 1);
        glo += __shfl_xor_sync(0xFFFFFFFFu, glo, 2);
        ghi += __shfl_xor_sync(0xFFFFFFFFu, ghi, 1);
        ghi += __shfl_xor_sync(0xFFFFFFFFu, ghi, 2);
        if (cq == 0) {
          const int br = (2 * wid + mt) * 16 + r0q;
          __stcg(&g_spart[d][br][c], glo);
          __stcg(&g_spart[d][br + 8][c], ghi);
        }
      }
    }
    __syncthreads();

    const int pos = d ? (kT - 1 - t) : t;
    const int nxt = cur ^ 1;

    ++gphase;
    if (tid == 0) gb_arrive(d, gphase, c);  // spart published

    float xv = 0.f;
    bool m = false;
    if (tid < 256) {  // overlap independent loads with barrier propagation
      xv = __ldg(&x[(size_t)eb * kT + pos]);
      const size_t midx = (size_t)eb * kT + pos;
      if (mmode == 1)
        m = ((const int*)mask)[midx] != 0;
      else if (mmode == 2)
        m = ((const float*)mask)[midx] != 0.f;
      else
        m = ((const uint8_t*)mask)[midx] != 0;
    }
    gb_wait(d, gphase, tid);
    __syncthreads();

    float onew[4];
    if (tid < 256) {
      // split spart gather: even lane sums CTAs 0..31, odd 32..63
      const float4* pp = reinterpret_cast<const float4*>(&g_spart[d][eb][0]);
      float a = 0.f;
#pragma unroll
      for (int q = 0; q < 8; ++q) {
        float4 v = __ldcg(pp + ehalf * 8 + q);
        a += v.x + v.y + v.z + v.w;
      }
      a += __shfl_xor_sync(0xFFFFFFFFu, a, 1);
      const float s = tanh_fast(a + sb[88]);
      const float xin = m ? s : xv;

      unsigned short hi16[4], lo16[4];
      const int jbase = ehalf * 4;
#pragma unroll
      for (int u = 0; u < 4; ++u) {
        const int jj = jbase + u;
        float gr =
            ghs[jj * kGhsStride + eb] + sb[jj] + fmaf(xin, sb[48 + jj], sb[24 + jj]);
        float gz = ghs[(8 + jj) * kGhsStride + eb] + sb[8 + jj] +
                   fmaf(xin, sb[48 + 8 + jj], sb[24 + 8 + jj]);
        float ghn = ghs[(16 + jj) * kGhsStride + eb] + sb[16 + jj];
        float gin = fmaf(xin, sb[48 + 16 + jj], sb[24 + 16 + jj]);
        float r = sigmoid_fast(gr);
        float z = sigmoid_fast(gz);
        float n = tanh_fast(fmaf(r, ghn, gin));
        float hnew = fmaf(z, hreg[u] - n, n);
        hreg[u] = hnew;
        onew[u] = hnew;
        __nv_bfloat16 h_hi = __float2bfloat16_rn(hnew);
        __nv_bfloat16 h_lo = __float2bfloat16_rn(hnew - __bfloat162float(h_hi));
        hi16[u] = __bfloat16_as_ushort(h_hi);
        lo16[u] = __bfloat16_as_ushort(h_lo);
      }
      uint2 vhi, vlo;
      vhi.x = (uint32_t)hi16[0] | ((uint32_t)hi16[1] << 16);
      vhi.y = (uint32_t)hi16[2] | ((uint32_t)hi16[3] << 16);
      vlo.x = (uint32_t)lo16[0] | ((uint32_t)lo16[1] << 16);
      vlo.y = (uint32_t)lo16[2] | ((uint32_t)lo16[3] << 16);
      __stcg(reinterpret_cast<uint2*>(&g_hb[d][nxt][0][eb][j0 + jbase]), vhi);
      __stcg(reinterpret_cast<uint2*>(&g_hb[d][nxt][1][eb][j0 + jbase]), vlo);
    }
    __syncthreads();

    ++gphase;
    if (tid == 0) gb_arrive(d, gphase, c);  // h' published
    if (tid < 256) {                        // overlap out store with barrier
      float* op =
          out + ((size_t)eb << 20) + ((size_t)pos << 10) + (d << 9) + j0 + ehalf * 4;
      *reinterpret_cast<float4*>(op) =
          make_float4(onew[0], onew[1], onew[2], onew[3]);
    }
    gb_wait(d, gphase, tid);
    __syncthreads();
    cur = nxt;
  }
}

extern "C" void kernel_launch(void* const* d_in, const int* in_sizes, int n_in,
                              void* d_out, int out_size) {
  const float* x = (const float*)d_in[0];
  const void* mask = (const void*)d_in[1];
  const float* wf_ih = (const float*)d_in[2];
  const float* wf_hh = (const float*)d_in[3];
  const float* bf_ih = (const float*)d_in[4];
  const float* bf_hh = (const float*)d_in[5];
  const float* wb_ih = (const float*)d_in[6];
  const float* wb_hh = (const float*)d_in[7];
  const float* bb_ih = (const float*)d_in[8];
  const float* bb_hh = (const float*)d_in[9];
  const float* p_w1 = (const float*)d_in[10];
  const float* p_b1 = (const float*)d_in[11];
  const float* p_w2 = (const float*)d_in[12];
  const float* p_b2 = (const float*)d_in[13];
  float* out = (float*)d_out;

  (void)in_sizes;
  (void)n_in;
  (void)out_size;

  cudaFuncSetAttribute(bidgru_kernel, cudaFuncAttributeMaxDynamicSharedMemorySize,
                       kSmemBytes);
  init_kernel<<<256, 256>>>(mask);
  bidgru_kernel<<<kNCta, kThreads, kSmemBytes>>>(x, mask, wf_ih, wf_hh, bf_ih,
                                                 bf_hh, wb_ih, wb_hh, bb_ih, bb_hh,
                                                 p_w1, p_b1, p_w2, p_b2, out);
}

// round 8
// speedup vs baseline: 1.9102x; 1.0737x over previous
#include <cuda_runtime.h>
#include <cuda_fp16.h>
#include <stdint.h>

// ---------------------------------------------------------------------------
// Bidirectional GRU w/ predictor feedback. B=128, T=1024, H=512.
// Persistent grid: 128 CTAs (64/dir), 384 thr, ~182KB SMEM (1 CTA/SM).
// C[128b x 32n] = h[128x512] @ W[32x512]^T via mma.sync m16n8k16 fp16,
// 2 products (h split hi/lo fp16, W single fp16; err ~2^-11 -> rel ~5e-5).
// Warps 0-3: MMA. Warps 4-7: stage even K-chunks (buf0); warps 8-11: odd
// (buf1); same warps run the epilogue (gates, h update, outputs).
// NO global h barrier: each staging thread polls exactly the one producer
// CTA flag its uint4 depends on (chunk kc, lane q -> CTA 16kc+q). The spart
// exchange keeps a flag per CTA, published right after the predictor tiles
// of the last chunk, overlapped with the remaining gate MMAs.
// ---------------------------------------------------------------------------

namespace {
constexpr int kB = 128;
constexpr int kT = 1024;
constexpr int kH = 512;
constexpr int kCtaPerDir = 64;
constexpr int kNCta = 2 * kCtaPerDir;
constexpr int kThreads = 384;

// SMEM layout (bytes). Word strides % 32 == 4 -> conflict-free.
constexpr int kWStride = 520;                    // fp16 per W row (512+8)
constexpr int kWBytes = 32 * kWStride * 2;       // 33280
constexpr int kABase = kWBytes;
constexpr int kARow = 272;                       // bytes per A row (128k fp16 + pad)
constexpr int kAPart = kB * kARow;               // 34816
constexpr int kGhs = kABase + 4 * kAPart;        // 172544  ([24][132] f32)
constexpr int kGhsStride = 132;                  // words
constexpr int kSb = kGhs + 24 * kGhsStride * 4;  // 185216  (96 f32 biases)
constexpr int kSmemBytes = 186368;               // 1 CTA/SM (2x > 228KB)
}  // namespace

// Device-global scratch (no allocation allowed).
__device__ __align__(16) __half g_h[2][2][2][kB][kH];  // [dir][buf][part][b][k]
__device__ float g_spart[2][kB][kCtaPerDir];
__device__ unsigned int g_hflag[2][kCtaPerDir * 8];  // h step counters
__device__ unsigned int g_sflag[2][kCtaPerDir * 8];  // spart step counters
__device__ int g_mask_mode;                          // 0=u8, 1=i32, 2=f32

__device__ __forceinline__ float sigmoid_fast(float v) {
  return __fdividef(1.f, 1.f + __expf(-v));
}
__device__ __forceinline__ float tanh_fast(float v) {
  return 1.f - __fdividef(2.f, 1.f + __expf(2.f * v));
}
__device__ __forceinline__ uint32_t smem_u32(const void* p) {
  uint32_t a;
  asm("{ .reg .u64 t; cvta.to.shared.u64 t, %1; cvt.u32.u64 %0, t; }"
      : "=r"(a) : "l"(p));
  return a;
}
__device__ __forceinline__ void mma16816(float* d, uint32_t a0, uint32_t a1,
                                         uint32_t a2, uint32_t a3, uint32_t b0,
                                         uint32_t b1) {
  asm volatile(
      "mma.sync.aligned.m16n8k16.row.col.f32.f16.f16.f32 "
      "{%0,%1,%2,%3},{%4,%5,%6,%7},{%8,%9},{%0,%1,%2,%3};"
      : "+f"(d[0]), "+f"(d[1]), "+f"(d[2]), "+f"(d[3])
      : "r"(a0), "r"(a1), "r"(a2), "r"(a3), "r"(b0), "r"(b1));
}
#define LDM4(r, addr)                                                  \
  asm volatile(                                                        \
      "ldmatrix.sync.aligned.m8n8.x4.shared.b16 {%0,%1,%2,%3}, [%4];"  \
      : "=r"((r)[0]), "=r"((r)[1]), "=r"((r)[2]), "=r"((r)[3])         \
      : "r"(addr))

__device__ __forceinline__ void bar_sync(int id, int cnt) {
  asm volatile("bar.sync %0, %1;" ::"r"(id), "r"(cnt) : "memory");
}
__device__ __forceinline__ void bar_arrive(int id, int cnt) {
  asm volatile("bar.arrive %0, %1;" ::"r"(id), "r"(cnt) : "memory");
}
__device__ __forceinline__ unsigned int poll_ge(const unsigned int* fp,
                                                unsigned int need) {
  unsigned int v;
  do {
    asm volatile("ld.acquire.gpu.u32 %0, [%1];" : "=r"(v) : "l"(fp) : "memory");
  } while (v < need);
  return v;
}
__device__ __forceinline__ void flag_store(unsigned int* fp, unsigned int val) {
  asm volatile("fence.acq_rel.gpu;" ::: "memory");
  asm volatile("st.release.gpu.u32 [%0], %1;" ::"l"(fp), "r"(val) : "memory");
}

__global__ void init_kernel(const void* __restrict__ mask) {
  int idx = blockIdx.x * blockDim.x + threadIdx.x;  // 65536 threads
  reinterpret_cast<uint4*>(&g_h[0][0][0][0][0])[idx] = make_uint4(0, 0, 0, 0);
  if (idx < 2 * kCtaPerDir * 8) {
    (&g_hflag[0][0])[idx] = 0u;
    (&g_sflag[0][0])[idx] = 0u;
  }
  if (idx == 0) {
    const int* i32 = (const int*)mask;
    const float* f32 = (const float*)mask;
    bool is_i32 = true, is_f32 = true;
    for (int i = 0; i < 64; ++i) {
      int v = i32[i];
      if (v != 0 && v != 1) is_i32 = false;
      float f = f32[i];
      if (!(f == 0.f || f == 1.f)) is_f32 = false;
    }
    g_mask_mode = is_i32 ? 1 : (is_f32 ? 2 : 0);
  }
}

__global__ void __launch_bounds__(kThreads, 1)
bidgru_kernel(const float* __restrict__ x, const void* __restrict__ mask,
              const float* __restrict__ wf_ih, const float* __restrict__ wf_hh,
              const float* __restrict__ bf_ih, const float* __restrict__ bf_hh,
              const float* __restrict__ wb_ih, const float* __restrict__ wb_hh,
              const float* __restrict__ bb_ih, const float* __restrict__ bb_hh,
              const float* __restrict__ p_w1, const float* __restrict__ p_b1,
              const float* __restrict__ p_w2, const float* __restrict__ p_b2,
              float* __restrict__ out) {
  extern __shared__ __align__(16) char smem_c[];
  const uint32_t smem_base = smem_u32(smem_c);
  float* sb = reinterpret_cast<float*>(smem_c + kSb);
  float* ghs = reinterpret_cast<float*>(smem_c + kGhs);

  const int tid = threadIdx.x;
  const int wid = tid >> 5;
  const int lane = tid & 31;
  const int d = blockIdx.x >> 6;
  const int c = blockIdx.x & 63;
  const int j0 = c * 8;

  const float* w_hh = d ? wb_hh : wf_hh;
  const float* w_ih = d ? wb_ih : wf_ih;
  const float* b_hh = d ? bb_hh : bf_hh;
  const float* b_ih = d ? bb_ih : bf_ih;
  const int mmode = g_mask_mode;

  // ---- one-time W staging: fp32 -> fp16, rows [n][k] stride 520 ----
  for (int i = tid; i < 32 * kH; i += kThreads) {
    int r = i >> 9, k = i & (kH - 1);
    float v = (r < 24) ? w_hh[((r >> 3) * kH + j0 + (r & 7)) * kH + k]
                       : p_w1[(j0 + (r & 7)) * kH + k];
    reinterpret_cast<__half*>(smem_c)[r * kWStride + k] = __float2half_rn(v);
  }
  if (tid < 24) {
    int g = tid >> 3, jj = tid & 7;
    sb[tid] = b_hh[g * kH + j0 + jj];
    sb[24 + tid] = b_ih[g * kH + j0 + jj];
    sb[48 + tid] = w_ih[g * kH + j0 + jj];
  } else if (tid < 32) {
    int jj = tid - 24;
    sb[72 + jj] = p_b1[j0 + jj];
    sb[80 + jj] = p_w2[j0 + jj];
  } else if (tid == 32) {
    sb[88] = p_b2[0];
  }
  __syncthreads();

  const bool is_mma = tid < 128;
  const int r0q = lane >> 2, cq = lane & 3;
  const int md = lane >> 3, mr = lane & 7;
  const uint32_t a_off = (uint32_t)(((md & 1) * 8 + mr) * kARow + (md >> 1) * 16);
  const uint32_t b_off =
      (uint32_t)((((md >> 1) * 8 + mr) * kWStride) * 2 + (md & 1) * 16);
  const uint32_t w_addr = smem_base;

  // epilogue/staging geometry (tid in [128,384))
  const int t1 = tid - 128;        // 0..255
  const int grp = t1 >> 7;         // 0: chunks 0,2 (buf0); 1: chunks 1,3 (buf1)
  const int s = t1 & 127;          // thread within group
  const int qidx = s & 15;         // fixed uint4 k-slot -> producer CTA 16kc+qidx
  const int eb = t1 >> 1, ehalf = t1 & 1;
  float hreg[4] = {0.f, 0.f, 0.f, 0.f};
  unsigned int hseen0 = 0, hseen1 = 0, sseen = 0;

  int cur = 0;

  for (int t = 0; t < kT; ++t) {
    const int pos = d ? (kT - 1 - t) : t;
    const int nxt = cur ^ 1;

    if (is_mma) {
      // ================= MMA warps =================
      float acc[2][4][4];
#pragma unroll
      for (int mt = 0; mt < 2; ++mt)
#pragma unroll
        for (int nt = 0; nt < 4; ++nt)
#pragma unroll
          for (int q = 0; q < 4; ++q) acc[mt][nt][q] = 0.f;

#pragma unroll
      for (int kc = 0; kc < 4; ++kc) {
        const int buf = kc & 1;
        bar_sync(1 + buf, 256);  // chunk staged
        const uint32_t ab_hi = smem_base + kABase + (buf * 2) * kAPart;
        const uint32_t ab_lo = ab_hi + kAPart;
        const uint32_t bko = (uint32_t)(kc * 256);

        if (kc < 3) {
#pragma unroll
          for (int ks = 0; ks < 8; ++ks) {
            uint32_t ah[2][4], al[2][4];
#pragma unroll
            for (int mt = 0; mt < 2; ++mt) {
              uint32_t ao =
                  a_off + (uint32_t)((2 * wid + mt) * 16 * kARow + ks * 32);
              LDM4(ah[mt], ab_hi + ao);
              LDM4(al[mt], ab_lo + ao);
            }
#pragma unroll
            for (int np = 0; np < 2; ++np) {
              uint32_t bv[4];
              uint32_t bo = b_off + (uint32_t)(np * 16 * kWStride * 2) + bko +
                            (uint32_t)(ks * 32);
              LDM4(bv, w_addr + bo);
#pragma unroll
              for (int nti = 0; nti < 2; ++nti) {
                const int nt = np * 2 + nti;
                uint32_t B0 = bv[nti * 2], B1 = bv[nti * 2 + 1];
#pragma unroll
                for (int mt = 0; mt < 2; ++mt) {
                  mma16816(acc[mt][nt], ah[mt][0], ah[mt][1], ah[mt][2],
                           ah[mt][3], B0, B1);
                  mma16816(acc[mt][nt], al[mt][0], al[mt][1], al[mt][2],
                           al[mt][3], B0, B1);
                }
              }
            }
          }
        } else {
          // pass 1: np=1 (n-tiles 2,3 incl. predictor) -> publish spart early
#pragma unroll
          for (int ks = 0; ks < 8; ++ks) {
            uint32_t ah[2][4], al[2][4];
#pragma unroll
            for (int mt = 0; mt < 2; ++mt) {
              uint32_t ao =
                  a_off + (uint32_t)((2 * wid + mt) * 16 * kARow + ks * 32);
              LDM4(ah[mt], ab_hi + ao);
              LDM4(al[mt], ab_lo + ao);
            }
            uint32_t bv[4];
            uint32_t bo = b_off + (uint32_t)(16 * kWStride * 2) + bko +
                          (uint32_t)(ks * 32);
            LDM4(bv, w_addr + bo);
#pragma unroll
            for (int nti = 0; nti < 2; ++nti) {
              const int nt = 2 + nti;
              uint32_t B0 = bv[nti * 2], B1 = bv[nti * 2 + 1];
#pragma unroll
              for (int mt = 0; mt < 2; ++mt) {
                mma16816(acc[mt][nt], ah[mt][0], ah[mt][1], ah[mt][2], ah[mt][3],
                         B0, B1);
                mma16816(acc[mt][nt], al[mt][0], al[mt][1], al[mt][2], al[mt][3],
                         B0, B1);
              }
            }
          }
          {  // spart from acc[.][3] + flag (overlapped with pass 2)
            const float b1a = sb[72 + 2 * cq], b1b = sb[72 + 2 * cq + 1];
            const float w2a = sb[80 + 2 * cq], w2b = sb[80 + 2 * cq + 1];
#pragma unroll
            for (int mt = 0; mt < 2; ++mt) {
              float glo = fmaxf(acc[mt][3][0] + b1a, 0.f) * w2a +
                          fmaxf(acc[mt][3][1] + b1b, 0.f) * w2b;
              float ghi = fmaxf(acc[mt][3][2] + b1a, 0.f) * w2a +
                          fmaxf(acc[mt][3][3] + b1b, 0.f) * w2b;
              glo += __shfl_xor_sync(0xFFFFFFFFu, glo, 1);
              glo += __shfl_xor_sync(0xFFFFFFFFu, glo, 2);
              ghi += __shfl_xor_sync(0xFFFFFFFFu, ghi, 1);
              ghi += __shfl_xor_sync(0xFFFFFFFFu, ghi, 2);
              if (cq == 0) {
                const int br = (2 * wid + mt) * 16 + r0q;
                __stcg(&g_spart[d][br][c], glo);
                __stcg(&g_spart[d][br + 8][c], ghi);
              }
            }
            bar_sync(6, 128);
            if (tid == 0) flag_store(&g_sflag[d][c * 8], (unsigned)(t + 1));
          }
          // pass 2: np=0 (gate n-tiles 0,1)
#pragma unroll
          for (int ks = 0; ks < 8; ++ks) {
            uint32_t ah[2][4], al[2][4];
#pragma unroll
            for (int mt = 0; mt < 2; ++mt) {
              uint32_t ao =
                  a_off + (uint32_t)((2 * wid + mt) * 16 * kARow + ks * 32);
              LDM4(ah[mt], ab_hi + ao);
              LDM4(al[mt], ab_lo + ao);
            }
            uint32_t bv[4];
            uint32_t bo = b_off + bko + (uint32_t)(ks * 32);
            LDM4(bv, w_addr + bo);
#pragma unroll
            for (int nti = 0; nti < 2; ++nti) {
              uint32_t B0 = bv[nti * 2], B1 = bv[nti * 2 + 1];
#pragma unroll
              for (int mt = 0; mt < 2; ++mt) {
                mma16816(acc[mt][nti], ah[mt][0], ah[mt][1], ah[mt][2], ah[mt][3],
                         B0, B1);
                mma16816(acc[mt][nti], al[mt][0], al[mt][1], al[mt][2], al[mt][3],
                         B0, B1);
              }
            }
          }
        }
        bar_arrive(3 + buf, 256);  // buffer free
      }

      // scatter gate rows (n 0..23) to ghs, then signal epilogue
#pragma unroll
      for (int mt = 0; mt < 2; ++mt) {
        const int br = (2 * wid + mt) * 16 + r0q;
#pragma unroll
        for (int nt = 0; nt < 3; ++nt) {
          const int n0 = nt * 8 + cq * 2;
          ghs[n0 * kGhsStride + br] = acc[mt][nt][0];
          ghs[(n0 + 1) * kGhsStride + br] = acc[mt][nt][1];
          ghs[n0 * kGhsStride + br + 8] = acc[mt][nt][2];
          ghs[(n0 + 1) * kGhsStride + br + 8] = acc[mt][nt][3];
        }
      }
      bar_arrive(7, 384);
    } else {
      // ================= staging + epilogue warps =================
      const uint4* hb4 = reinterpret_cast<const uint4*>(&g_h[d][cur][0][0][0]);
#pragma unroll
      for (int kk = 0; kk < 2; ++kk) {
        const int kc = grp + 2 * kk;
        const int buf = grp;
        if (!(t == 0 && kk == 0)) bar_sync(3 + buf, 256);  // buffer free?
        const unsigned need = (unsigned)t;
        unsigned int& seen = kk ? hseen1 : hseen0;
        if (seen < need)
          seen = poll_ge(&g_hflag[d][(16 * kc + qidx) * 8], need);
#pragma unroll 8
        for (int i = 0; i < 32; ++i) {
          int u = i * 128 + s;
          int p = u >> 11, b = (u >> 4) & 127;
          uint4 v = __ldcg(hb4 + (p * kB + b) * 64 + kc * 16 + qidx);
          *reinterpret_cast<uint4*>(smem_c + kABase + (buf * 2 + p) * kAPart +
                                    b * kARow + qidx * 16) = v;
        }
        bar_arrive(1 + buf, 256);  // chunk staged
      }

      // ---- epilogue ----
      float xv = __ldg(&x[(size_t)eb * kT + pos]);
      bool m;
      {
        const size_t midx = (size_t)eb * kT + pos;
        if (mmode == 1)
          m = ((const int*)mask)[midx] != 0;
        else if (mmode == 2)
          m = ((const float*)mask)[midx] != 0.f;
        else
          m = ((const uint8_t*)mask)[midx] != 0;
      }
      if (sseen < (unsigned)(t + 1))
        sseen = poll_ge(&g_sflag[d][(t1 & 63) * 8], (unsigned)(t + 1));
      bar_sync(8, 256);  // all 64 spart flags observed collectively

      float a = 0.f;
      {
        const float4* pp = reinterpret_cast<const float4*>(&g_spart[d][eb][0]);
#pragma unroll
        for (int q = 0; q < 8; ++q) {
          float4 v = __ldcg(pp + ehalf * 8 + q);
          a += v.x + v.y + v.z + v.w;
        }
        a += __shfl_xor_sync(0xFFFFFFFFu, a, 1);
      }
      const float scal = tanh_fast(a + sb[88]);
      const float xin = m ? scal : xv;

      bar_sync(7, 384);  // ghs ready

      float onew[4];
      unsigned short hi16[4], lo16[4];
      const int jbase = ehalf * 4;
#pragma unroll
      for (int u = 0; u < 4; ++u) {
        const int jj = jbase + u;
        float gr = ghs[jj * kGhsStride + eb] + sb[jj] +
                   fmaf(xin, sb[48 + jj], sb[24 + jj]);
        float gz = ghs[(8 + jj) * kGhsStride + eb] + sb[8 + jj] +
                   fmaf(xin, sb[48 + 8 + jj], sb[24 + 8 + jj]);
        float ghn = ghs[(16 + jj) * kGhsStride + eb] + sb[16 + jj];
        float gin = fmaf(xin, sb[48 + 16 + jj], sb[24 + 16 + jj]);
        float r = sigmoid_fast(gr);
        float z = sigmoid_fast(gz);
        float n = tanh_fast(fmaf(r, ghn, gin));
        float hnew = fmaf(z, hreg[u] - n, n);
        hreg[u] = hnew;
        onew[u] = hnew;
        __half h_hi = __float2half_rn(hnew);
        __half h_lo = __float2half_rn(hnew - __half2float(h_hi));
        hi16[u] = __half_as_ushort(h_hi);
        lo16[u] = __half_as_ushort(h_lo);
      }
      uint2 vhi, vlo;
      vhi.x = (uint32_t)hi16[0] | ((uint32_t)hi16[1] << 16);
      vhi.y = (uint32_t)hi16[2] | ((uint32_t)hi16[3] << 16);
      vlo.x = (uint32_t)lo16[0] | ((uint32_t)lo16[1] << 16);
      vlo.y = (uint32_t)lo16[2] | ((uint32_t)lo16[3] << 16);
      __stcg(reinterpret_cast<uint2*>(&g_h[d][nxt][0][eb][j0 + jbase]), vhi);
      __stcg(reinterpret_cast<uint2*>(&g_h[d][nxt][1][eb][j0 + jbase]), vlo);

      bar_sync(9, 256);  // all h' stores done
      if (t1 == 0) flag_store(&g_hflag[d][c * 8], (unsigned)(t + 1));

      float* op =
          out + ((size_t)eb << 20) + ((size_t)pos << 10) + (d << 9) + j0 + jbase;
      *reinterpret_cast<float4*>(op) =
          make_float4(onew[0], onew[1], onew[2], onew[3]);
    }
    cur = nxt;
  }
}

extern "C" void kernel_launch(void* const* d_in, const int* in_sizes, int n_in,
                              void* d_out, int out_size) {
  const float* x = (const float*)d_in[0];
  const void* mask = (const void*)d_in[1];
  const float* wf_ih = (const float*)d_in[2];
  const float* wf_hh = (const float*)d_in[3];
  const float* bf_ih = (const float*)d_in[4];
  const float* bf_hh = (const float*)d_in[5];
  const float* wb_ih = (const float*)d_in[6];
  const float* wb_hh = (const float*)d_in[7];
  const float* bb_ih = (const float*)d_in[8];
  const float* bb_hh = (const float*)d_in[9];
  const float* p_w1 = (const float*)d_in[10];
  const float* p_b1 = (const float*)d_in[11];
  const float* p_w2 = (const float*)d_in[12];
  const float* p_b2 = (const float*)d_in[13];
  float* out = (float*)d_out;

  (void)in_sizes;
  (void)n_in;
  (void)out_size;

  cudaFuncSetAttribute(bidgru_kernel, cudaFuncAttributeMaxDynamicSharedMemorySize,
                       kSmemBytes);
  init_kernel<<<256, 256>>>(mask);
  bidgru_kernel<<<kNCta, kThreads, kSmemBytes>>>(x, mask, wf_ih, wf_hh, bf_ih,
                                                 bf_hh, wb_ih, wb_hh, bb_ih, bb_hh,
                                                 p_w1, p_b1, p_w2, p_b2, out);
}

// round 10
// speedup vs baseline: 2.9293x; 1.5335x over previous
#include <cuda_runtime.h>
#include <cuda_fp16.h>
#include <stdint.h>

// ---------------------------------------------------------------------------
// Bidirectional GRU w/ predictor feedback. B=128, T=1024, H=512.
// Persistent grid: 128 CTAs (64/dir), 384 thr, ~182KB SMEM (1 CTA/SM).
// C[128b x 32n] = h[128x512] @ W[32x512]^T via mma.sync m16n8k16 fp16,
// SINGLE product (h and W fp16; |h|<1, err ~2^-11 -> rel ~1e-4).
// Warps 0-3: MMA. Warps 4-11: stage K-chunks + epilogue.
// Cross-CTA sync via ONE aggregated counter per direction and kind
// (red.release.gpu.add by each CTA; exactly one thread per CTA polls).
// All 4 K-chunks are SMEM-resident: no intra-step buffer recycling bars.
// R10 fix: init_kernel zeroes ALL of g_h (32768 uint4, not 16384) — R9 left
// the backward-direction h buffers un-reset between graph replays.
// ---------------------------------------------------------------------------

namespace {
constexpr int kB = 128;
constexpr int kT = 1024;
constexpr int kH = 512;
constexpr int kCtaPerDir = 64;
constexpr int kNCta = 2 * kCtaPerDir;
constexpr int kThreads = 384;

// SMEM layout (bytes). Word strides % 32 == 4 -> conflict-free.
constexpr int kWStride = 520;                    // fp16 per W row (512+8)
constexpr int kWBytes = 32 * kWStride * 2;       // 33280
constexpr int kABase = kWBytes;
constexpr int kARow = 272;                       // bytes per A row (128k fp16 + pad)
constexpr int kAPart = kB * kARow;               // 34816
constexpr int kGhs = kABase + 4 * kAPart;        // 172544  ([24][132] f32)
constexpr int kGhsStride = 132;                  // words
constexpr int kSb = kGhs + 24 * kGhsStride * 4;  // 185216  (96 f32 biases)
constexpr int kSmemBytes = 186368;               // 1 CTA/SM (2x > 228KB)
}  // namespace

// Device-global scratch (no allocation allowed).
__device__ __align__(16) __half g_h[2][2][kB][kH];  // [dir][buf][b][k], fp16
__device__ float g_spart[2][kB][kCtaPerDir];
__device__ unsigned int g_hcnt[2][32];  // aggregated h counters (line-padded)
__device__ unsigned int g_scnt[2][32];  // aggregated spart counters
__device__ int g_mask_mode;             // 0=u8, 1=i32, 2=f32

__device__ __forceinline__ float sigmoid_fast(float v) {
  return __fdividef(1.f, 1.f + __expf(-v));
}
__device__ __forceinline__ float tanh_fast(float v) {
  return 1.f - __fdividef(2.f, 1.f + __expf(2.f * v));
}
__device__ __forceinline__ uint32_t smem_u32(const void* p) {
  uint32_t a;
  asm("{ .reg .u64 t; cvta.to.shared.u64 t, %1; cvt.u32.u64 %0, t; }"
      : "=r"(a) : "l"(p));
  return a;
}
__device__ __forceinline__ void mma16816(float* d, uint32_t a0, uint32_t a1,
                                         uint32_t a2, uint32_t a3, uint32_t b0,
                                         uint32_t b1) {
  asm volatile(
      "mma.sync.aligned.m16n8k16.row.col.f32.f16.f16.f32 "
      "{%0,%1,%2,%3},{%4,%5,%6,%7},{%8,%9},{%0,%1,%2,%3};"
      : "+f"(d[0]), "+f"(d[1]), "+f"(d[2]), "+f"(d[3])
      : "r"(a0), "r"(a1), "r"(a2), "r"(a3), "r"(b0), "r"(b1));
}
#define LDM4(r, addr)                                                  \
  asm volatile(                                                        \
      "ldmatrix.sync.aligned.m8n8.x4.shared.b16 {%0,%1,%2,%3}, [%4];"  \
      : "=r"((r)[0]), "=r"((r)[1]), "=r"((r)[2]), "=r"((r)[3])         \
      : "r"(addr))

__device__ __forceinline__ void bar_sync(int id, int cnt) {
  asm volatile("bar.sync %0, %1;" ::"r"(id), "r"(cnt) : "memory");
}
__device__ __forceinline__ void bar_arrive(int id, int cnt) {
  asm volatile("bar.arrive %0, %1;" ::"r"(id), "r"(cnt) : "memory");
}
__device__ __forceinline__ unsigned int poll_ge(const unsigned int* fp,
                                                unsigned int need) {
  unsigned int v;
  do {
    asm volatile("ld.acquire.gpu.u32 %0, [%1];" : "=r"(v) : "l"(fp) : "memory");
  } while ((int)(v - need) < 0);
  return v;
}
__device__ __forceinline__ void cnt_bump(unsigned int* cp) {
  asm volatile("fence.acq_rel.gpu;" ::: "memory");
  asm volatile("red.release.gpu.global.add.u32 [%0], 1;" ::"l"(cp) : "memory");
}

__global__ void init_kernel(const void* __restrict__ mask) {
  int idx = blockIdx.x * blockDim.x + threadIdx.x;  // 65536 threads
  if (idx < 32768)  // g_h = 2*2*128*512 halfs = 512KB = 32768 uint4
    reinterpret_cast<uint4*>(&g_h[0][0][0][0])[idx] = make_uint4(0, 0, 0, 0);
  if (idx < 64) {
    (&g_hcnt[0][0])[idx] = 0u;
    (&g_scnt[0][0])[idx] = 0u;
  }
  if (idx == 0) {
    const int* i32 = (const int*)mask;
    const float* f32 = (const float*)mask;
    bool is_i32 = true, is_f32 = true;
    for (int i = 0; i < 64; ++i) {
      int v = i32[i];
      if (v != 0 && v != 1) is_i32 = false;
      float f = f32[i];
      if (!(f == 0.f || f == 1.f)) is_f32 = false;
    }
    g_mask_mode = is_i32 ? 1 : (is_f32 ? 2 : 0);
  }
}

__global__ void __launch_bounds__(kThreads, 1)
bidgru_kernel(const float* __restrict__ x, const void* __restrict__ mask,
              const float* __restrict__ wf_ih, const float* __restrict__ wf_hh,
              const float* __restrict__ bf_ih, const float* __restrict__ bf_hh,
              const float* __restrict__ wb_ih, const float* __restrict__ wb_hh,
              const float* __restrict__ bb_ih, const float* __restrict__ bb_hh,
              const float* __restrict__ p_w1, const float* __restrict__ p_b1,
              const float* __restrict__ p_w2, const float* __restrict__ p_b2,
              float* __restrict__ out) {
  extern __shared__ __align__(16) char smem_c[];
  const uint32_t smem_base = smem_u32(smem_c);
  float* sb = reinterpret_cast<float*>(smem_c + kSb);
  float* ghs = reinterpret_cast<float*>(smem_c + kGhs);

  const int tid = threadIdx.x;
  const int wid = tid >> 5;
  const int lane = tid & 31;
  const int d = blockIdx.x >> 6;
  const int c = blockIdx.x & 63;
  const int j0 = c * 8;

  const float* w_hh = d ? wb_hh : wf_hh;
  const float* w_ih = d ? wb_ih : wf_ih;
  const float* b_hh = d ? bb_hh : bf_hh;
  const float* b_ih = d ? bb_ih : bf_ih;
  const int mmode = g_mask_mode;

  // ---- one-time W staging: fp32 -> fp16, rows [n][k] stride 520 ----
  for (int i = tid; i < 32 * kH; i += kThreads) {
    int r = i >> 9, k = i & (kH - 1);
    float v = (r < 24) ? w_hh[((r >> 3) * kH + j0 + (r & 7)) * kH + k]
                       : p_w1[(j0 + (r & 7)) * kH + k];
    reinterpret_cast<__half*>(smem_c)[r * kWStride + k] = __float2half_rn(v);
  }
  if (tid < 24) {
    int g = tid >> 3, jj = tid & 7;
    sb[tid] = b_hh[g * kH + j0 + jj];
    sb[24 + tid] = b_ih[g * kH + j0 + jj];
    sb[48 + tid] = w_ih[g * kH + j0 + jj];
  } else if (tid < 32) {
    int jj = tid - 24;
    sb[72 + jj] = p_b1[j0 + jj];
    sb[80 + jj] = p_w2[j0 + jj];
  } else if (tid == 32) {
    sb[88] = p_b2[0];
  }
  __syncthreads();

  const bool is_mma = tid < 128;
  const int r0q = lane >> 2, cq = lane & 3;
  const int md = lane >> 3, mr = lane & 7;
  const uint32_t a_off = (uint32_t)(((md & 1) * 8 + mr) * kARow + (md >> 1) * 16);
  const uint32_t b_off =
      (uint32_t)((((md >> 1) * 8 + mr) * kWStride) * 2 + (md & 1) * 16);
  const uint32_t w_addr = smem_base;

  // staging/epilogue geometry (tid in [128,384))
  const int t1 = tid - 128;  // 0..255
  const int grp = t1 >> 7;   // group 0: chunks 0,2 ; group 1: chunks 1,3
  const int s = t1 & 127;
  const int q16 = s & 15, br0 = s >> 4;
  const int eb = t1 >> 1, ehalf = t1 & 1;
  float hreg[4] = {0.f, 0.f, 0.f, 0.f};

  unsigned int* hcnt = &g_hcnt[d][0];
  unsigned int* scnt = &g_scnt[d][0];

  int cur = 0;

  for (int t = 0; t < kT; ++t) {
    const int pos = d ? (kT - 1 - t) : t;
    const int nxt = cur ^ 1;

    if (is_mma) {
      // ================= MMA warps (0-3) =================
      float acc[2][4][4];
#pragma unroll
      for (int mt = 0; mt < 2; ++mt)
#pragma unroll
        for (int nt = 0; nt < 4; ++nt)
#pragma unroll
          for (int q = 0; q < 4; ++q) acc[mt][nt][q] = 0.f;

#pragma unroll
      for (int kc = 0; kc < 4; ++kc) {
        bar_sync(1 + kc, 256);  // chunk kc staged
        const uint32_t ab = smem_base + kABase + kc * kAPart;
        const uint32_t bko = (uint32_t)(kc * 256);

        if (kc < 3) {
#pragma unroll
          for (int ks = 0; ks < 8; ++ks) {
            uint32_t ah[2][4];
#pragma unroll
            for (int mt = 0; mt < 2; ++mt)
              LDM4(ah[mt],
                   ab + a_off + (uint32_t)((2 * wid + mt) * 16 * kARow + ks * 32));
#pragma unroll
            for (int np = 0; np < 2; ++np) {
              uint32_t bv[4];
              LDM4(bv, w_addr + b_off + (uint32_t)(np * 16 * kWStride * 2) + bko +
                           (uint32_t)(ks * 32));
#pragma unroll
              for (int nti = 0; nti < 2; ++nti) {
                const int nt = np * 2 + nti;
#pragma unroll
                for (int mt = 0; mt < 2; ++mt)
                  mma16816(acc[mt][nt], ah[mt][0], ah[mt][1], ah[mt][2],
                           ah[mt][3], bv[nti * 2], bv[nti * 2 + 1]);
              }
            }
          }
        } else {
          // pass 1: np=1 (n-tiles 2,3 incl. predictor rows)
#pragma unroll
          for (int ks = 0; ks < 8; ++ks) {
            uint32_t ah[2][4];
#pragma unroll
            for (int mt = 0; mt < 2; ++mt)
              LDM4(ah[mt],
                   ab + a_off + (uint32_t)((2 * wid + mt) * 16 * kARow + ks * 32));
            uint32_t bv[4];
            LDM4(bv, w_addr + b_off + (uint32_t)(16 * kWStride * 2) + bko +
                         (uint32_t)(ks * 32));
#pragma unroll
            for (int nti = 0; nti < 2; ++nti) {
              const int nt = 2 + nti;
#pragma unroll
              for (int mt = 0; mt < 2; ++mt)
                mma16816(acc[mt][nt], ah[mt][0], ah[mt][1], ah[mt][2], ah[mt][3],
                         bv[nti * 2], bv[nti * 2 + 1]);
            }
          }
          {  // publish spart early (overlaps with pass 2)
            const float b1a = sb[72 + 2 * cq], b1b = sb[72 + 2 * cq + 1];
            const float w2a = sb[80 + 2 * cq], w2b = sb[80 + 2 * cq + 1];
#pragma unroll
            for (int mt = 0; mt < 2; ++mt) {
              float glo = fmaxf(acc[mt][3][0] + b1a, 0.f) * w2a +
                          fmaxf(acc[mt][3][1] + b1b, 0.f) * w2b;
              float ghi = fmaxf(acc[mt][3][2] + b1a, 0.f) * w2a +
                          fmaxf(acc[mt][3][3] + b1b, 0.f) * w2b;
              glo += __shfl_xor_sync(0xFFFFFFFFu, glo, 1);
              glo += __shfl_xor_sync(0xFFFFFFFFu, glo, 2);
              ghi += __shfl_xor_sync(0xFFFFFFFFu, ghi, 1);
              ghi += __shfl_xor_sync(0xFFFFFFFFu, ghi, 2);
              if (cq == 0) {
                const int br = (2 * wid + mt) * 16 + r0q;
                __stcg(&g_spart[d][br][c], glo);
                __stcg(&g_spart[d][br + 8][c], ghi);
              }
            }
            bar_sync(6, 128);
            if (tid == 0) cnt_bump(scnt);
          }
          // pass 2: np=0 (gate n-tiles 0,1)
#pragma unroll
          for (int ks = 0; ks < 8; ++ks) {
            uint32_t ah[2][4];
#pragma unroll
            for (int mt = 0; mt < 2; ++mt)
              LDM4(ah[mt],
                   ab + a_off + (uint32_t)((2 * wid + mt) * 16 * kARow + ks * 32));
            uint32_t bv[4];
            LDM4(bv, w_addr + b_off + bko + (uint32_t)(ks * 32));
#pragma unroll
            for (int nti = 0; nti < 2; ++nti) {
#pragma unroll
              for (int mt = 0; mt < 2; ++mt)
                mma16816(acc[mt][nti], ah[mt][0], ah[mt][1], ah[mt][2], ah[mt][3],
                         bv[nti * 2], bv[nti * 2 + 1]);
            }
          }
        }
      }

      // scatter gate rows (n 0..23) to ghs, then signal epilogue
#pragma unroll
      for (int mt = 0; mt < 2; ++mt) {
        const int br = (2 * wid + mt) * 16 + r0q;
#pragma unroll
        for (int nt = 0; nt < 3; ++nt) {
          const int n0 = nt * 8 + cq * 2;
          ghs[n0 * kGhsStride + br] = acc[mt][nt][0];
          ghs[(n0 + 1) * kGhsStride + br] = acc[mt][nt][1];
          ghs[n0 * kGhsStride + br + 8] = acc[mt][nt][2];
          ghs[(n0 + 1) * kGhsStride + br + 8] = acc[mt][nt][3];
        }
      }
      bar_arrive(7, 384);
    } else {
      // ================= staging + epilogue warps (4-11) =================
      // gate: all CTAs published h_{t-1}  (counter == 64*t)
      if (t > 0) {
        if (t1 == 0) poll_ge(hcnt, (unsigned)(64 * t));
        bar_sync(5, 256);
      }
      const uint4* hb4 = reinterpret_cast<const uint4*>(&g_h[d][cur][0][0]);
#pragma unroll
      for (int kk = 0; kk < 2; ++kk) {
        const int kc = grp + 2 * kk;
#pragma unroll 4
        for (int i = 0; i < 16; ++i) {
          const int b = i * 8 + br0;
          uint4 v = __ldcg(hb4 + b * 64 + kc * 16 + q16);
          *reinterpret_cast<uint4*>(smem_c + kABase + kc * kAPart + b * kARow +
                                    q16 * 16) = v;
        }
        bar_arrive(1 + kc, 256);  // chunk staged
      }

      // ---- epilogue ----
      float xv = __ldg(&x[(size_t)eb * kT + pos]);
      bool m;
      {
        const size_t midx = (size_t)eb * kT + pos;
        if (mmode == 1)
          m = ((const int*)mask)[midx] != 0;
        else if (mmode == 2)
          m = ((const float*)mask)[midx] != 0.f;
        else
          m = ((const uint8_t*)mask)[midx] != 0;
      }
      // gate: all CTAs published spart_t (counter == 64*(t+1))
      if (t1 == 0) poll_ge(scnt, (unsigned)(64 * (t + 1)));
      bar_sync(8, 256);

      float a = 0.f;
      {
        const float4* pp = reinterpret_cast<const float4*>(&g_spart[d][eb][0]);
#pragma unroll
        for (int q = 0; q < 8; ++q) {
          float4 v = __ldcg(pp + ehalf * 8 + q);
          a += v.x + v.y + v.z + v.w;
        }
        a += __shfl_xor_sync(0xFFFFFFFFu, a, 1);
      }
      const float scal = tanh_fast(a + sb[88]);
      const float xin = m ? scal : xv;

      bar_sync(7, 384);  // ghs ready

      float onew[4];
      unsigned short h16[4];
      const int jbase = ehalf * 4;
#pragma unroll
      for (int u = 0; u < 4; ++u) {
        const int jj = jbase + u;
        float gr = ghs[jj * kGhsStride + eb] + sb[jj] +
                   fmaf(xin, sb[48 + jj], sb[24 + jj]);
        float gz = ghs[(8 + jj) * kGhsStride + eb] + sb[8 + jj] +
                   fmaf(xin, sb[48 + 8 + jj], sb[24 + 8 + jj]);
        float ghn = ghs[(16 + jj) * kGhsStride + eb] + sb[16 + jj];
        float gin = fmaf(xin, sb[48 + 16 + jj], sb[24 + 16 + jj]);
        float r = sigmoid_fast(gr);
        float z = sigmoid_fast(gz);
        float n = tanh_fast(fmaf(r, ghn, gin));
        float hnew = fmaf(z, hreg[u] - n, n);
        hreg[u] = hnew;
        onew[u] = hnew;
        h16[u] = __half_as_ushort(__float2half_rn(hnew));
      }
      uint2 vh;
      vh.x = (uint32_t)h16[0] | ((uint32_t)h16[1] << 16);
      vh.y = (uint32_t)h16[2] | ((uint32_t)h16[3] << 16);
      __stcg(reinterpret_cast<uint2*>(&g_h[d][nxt][eb][j0 + jbase]), vh);

      bar_sync(9, 256);  // all h' stores issued
      if (t1 == 0) cnt_bump(hcnt);

      float* op =
          out + ((size_t)eb << 20) + ((size_t)pos << 10) + (d << 9) + j0 + jbase;
      *reinterpret_cast<float4*>(op) =
          make_float4(onew[0], onew[1], onew[2], onew[3]);
    }
    cur = nxt;
  }
}

extern "C" void kernel_launch(void* const* d_in, const int* in_sizes, int n_in,
                              void* d_out, int out_size) {
  const float* x = (const float*)d_in[0];
  const void* mask = (const void*)d_in[1];
  const float* wf_ih = (const float*)d_in[2];
  const float* wf_hh = (const float*)d_in[3];
  const float* bf_ih = (const float*)d_in[4];
  const float* bf_hh = (const float*)d_in[5];
  const float* wb_ih = (const float*)d_in[6];
  const float* wb_hh = (const float*)d_in[7];
  const float* bb_ih = (const float*)d_in[8];
  const float* bb_hh = (const float*)d_in[9];
  const float* p_w1 = (const float*)d_in[10];
  const float* p_b1 = (const float*)d_in[11];
  const float* p_w2 = (const float*)d_in[12];
  const float* p_b2 = (const float*)d_in[13];
  float* out = (float*)d_out;

  (void)in_sizes;
  (void)n_in;
  (void)out_size;

  cudaFuncSetAttribute(bidgru_kernel, cudaFuncAttributeMaxDynamicSharedMemorySize,
                       kSmemBytes);
  init_kernel<<<256, 256>>>(mask);
  bidgru_kernel<<<kNCta, kThreads, kSmemBytes>>>(x, mask, wf_ih, wf_hh, bf_ih,
                                                 bf_hh, wb_ih, wb_hh, bb_ih, bb_hh,
                                                 p_w1, p_b1, p_w2, p_b2, out);
}